// round 11
// baseline (speedup 1.0000x reference)
#include <cuda_runtime.h>
#include <cuda_bf16.h>

#define NODES_MAX 50000
#define FEATS 128
#define KNBR 20
#define NTILES_MAX ((NODES_MAX + 127) / 128)

// Tiled+swizzled bf16 planes in gmem, ready for cp.async.bulk:
// per tile 65536B = [khalf0: hi 16KB | lo 16KB][khalf1: hi 16KB | lo 16KB]
__device__ __align__(128) unsigned char g_Vt[NTILES_MAX * 65536];
__device__ __align__(128) unsigned char g_Gt[NTILES_MAX * 65536];

// =================== helpers ===================
__device__ __forceinline__ unsigned int smem_u32(const void* p) {
    unsigned int a;
    asm("{ .reg .u64 t; cvta.to.shared.u64 t, %1; cvt.u32.u64 %0, t; }"
        : "=r"(a) : "l"(p));
    return a;
}
__device__ __forceinline__ void ldsm4(unsigned int r[4], unsigned int addr) {
    asm volatile("ldmatrix.sync.aligned.m8n8.x4.shared.b16 {%0,%1,%2,%3}, [%4];"
                 : "=r"(r[0]), "=r"(r[1]), "=r"(r[2]), "=r"(r[3])
                 : "r"(addr));
}
__device__ __forceinline__ void mma16816(float c[4], const unsigned int a[4],
                                         unsigned int b0, unsigned int b1) {
    asm volatile(
        "mma.sync.aligned.m16n8k16.row.col.f32.bf16.bf16.f32 "
        "{%0,%1,%2,%3}, {%4,%5,%6,%7}, {%8,%9}, {%0,%1,%2,%3};"
        : "+f"(c[0]), "+f"(c[1]), "+f"(c[2]), "+f"(c[3])
        : "r"(a[0]), "r"(a[1]), "r"(a[2]), "r"(a[3]), "r"(b0), "r"(b1));
}

#define MBARRIER_INIT(mbar, cnt) \
    asm volatile("mbarrier.init.shared.b64 [%0], %1;" :: "r"(mbar), "r"(cnt) : "memory")
#define MBAR_EXPECT_TX(mbar, bytes) \
    asm volatile("mbarrier.arrive.expect_tx.shared.b64 _, [%0], %1;" \
                 :: "r"(mbar), "r"(bytes) : "memory")
#define BULK_G2S(dst, src, bytes, mbar) \
    asm volatile("cp.async.bulk.shared::cluster.global.mbarrier::complete_tx::bytes " \
                 "[%0], [%1], %2, [%3];" \
                 :: "r"(dst), "l"(src), "r"(bytes), "r"(mbar) : "memory")

#define MBARRIER_WAIT_PARITY(mbar, parity) do {                                   \
    unsigned int _m = (mbar); unsigned int _p = (parity); unsigned int _d;        \
    asm volatile("{\n\t.reg .pred p;\n\t"                                         \
        "mbarrier.try_wait.parity.acquire.cta.shared::cta.b64 p, [%1], %2;\n\t"   \
        "selp.b32 %0, 1, 0, p;\n\t}"                                              \
        : "=r"(_d) : "r"(_m), "r"(_p) : "memory");                                \
    if (!_d) {                                                                    \
        asm volatile("{\n\t.reg .pred P1;\n\t"                                    \
            "WAIT_LOOP_%=:\n\t"                                                   \
            "mbarrier.try_wait.parity.acquire.cta.shared::cta.b64 P1, [%0], %1, 0x989680;\n\t" \
            "@P1 bra.uni WAIT_DONE_%=;\n\t"                                       \
            "bra.uni WAIT_LOOP_%=;\n\t"                                           \
            "WAIT_DONE_%=:\n\t}"                                                  \
            :: "r"(_m), "r"(_p) : "memory");                                      \
    }                                                                             \
} while (0)

__device__ __forceinline__ unsigned int sw128(unsigned int b) {
    return b ^ ((b >> 3) & 0x70);
}
// [128 x 128] bf16 K-major tile = two 64-k planes of 16KB, 128B rows
__device__ __forceinline__ unsigned int tile_off(int row, int k) {
    return ((unsigned)(k >> 6) << 14) + ((unsigned)row << 7) + ((unsigned)(k & 63) << 1);
}
// byte offset of (node, k4-group) hi element inside g_Vt/g_Gt (lo at +16384)
__device__ __forceinline__ unsigned int tiled_off(int node, int k4) {
    int tile = node >> 7, row = node & 127, h = k4 >> 4;
    unsigned int off = sw128((unsigned)(row * 128 + (k4 & 15) * 8));
    return ((unsigned)tile << 16) + ((unsigned)h << 15) + off;
}
__device__ __forceinline__ unsigned int pack2bf(float a, float b) {
    __nv_bfloat162 p = __floats2bfloat162_rn(a, b);
    return *reinterpret_cast<unsigned int*>(&p);
}

// ---------------- Kernel 0: V -> tiled bf16 hi/lo planes ----------------
__global__ void conv_kernel(const float4* __restrict__ X4, int n4) {
    int i = blockIdx.x * blockDim.x + threadIdx.x;
    if (i < n4) {
        int node = i >> 5, k4 = i & 31;
        float4 v = X4[i];
        float vv[4] = {v.x, v.y, v.z, v.w};
        float hf[4];
#pragma unroll
        for (int q = 0; q < 4; q++)
            hf[q] = __bfloat162float(__float2bfloat16(vv[q]));
        uint2 hi = make_uint2(pack2bf(hf[0], hf[1]), pack2bf(hf[2], hf[3]));
        uint2 lo = make_uint2(pack2bf(vv[0] - hf[0], vv[1] - hf[1]),
                              pack2bf(vv[2] - hf[2], vv[3] - hf[3]));
        unsigned int o = tiled_off(node, k4);
        *reinterpret_cast<uint2*>(g_Vt + o) = hi;
        *reinterpret_cast<uint2*>(g_Vt + 16384 + o) = lo;
    }
}

// ---------------- Kernel 1: gather-aggregate from tiled bf16 V ----------------
__global__ void agg_kernel(const int* __restrict__ nh_idx,
                           const int* __restrict__ int_idx,
                           const float* __restrict__ nh_e,
                           const float* __restrict__ int_e,
                           int n) {
    int node = blockIdx.x * (blockDim.x >> 5) + (threadIdx.x >> 5);
    if (node >= n) return;
    int lane = threadIdx.x & 31;
    // per-lane constant parts of the tiled gather address
    const unsigned int hbase = ((unsigned)(lane >> 4) << 15);
    const unsigned int cpart = (unsigned)((lane & 15) * 8);

    int   iA = -1, iB = -1;
    float eA = 0.f, eB = 0.f;
    if (lane < KNBR) {
        int base = node * KNBR + lane;
        iA = nh_idx[base];
        eA = nh_e[base];
        iB = int_idx[base];
        eB = int_e[base];
    }
    int validB = __popc(__ballot_sync(0xffffffffu, (lane < KNBR) && (iB >= 0)));

    float4 acc = make_float4(0.f, 0.f, 0.f, 0.f);
#pragma unroll
    for (int j = 0; j < KNBR; j++) {
        int   idx = __shfl_sync(0xffffffffu, iA, j);
        float e   = __shfl_sync(0xffffffffu, eA, j);
        int row = idx & 127;
        unsigned int o = ((unsigned)(idx >> 7) << 16) + hbase + ((unsigned)row << 7)
                       + (cpart ^ (((unsigned)row & 7) << 4));
        uint2 u = __ldg(reinterpret_cast<const uint2*>(g_Vt + o));
        __nv_bfloat162 p0 = *reinterpret_cast<__nv_bfloat162*>(&u.x);
        __nv_bfloat162 p1 = *reinterpret_cast<__nv_bfloat162*>(&u.y);
        acc.x = fmaf(e, __bfloat162float(p0.x), acc.x);
        acc.y = fmaf(e, __bfloat162float(p0.y), acc.y);
        acc.z = fmaf(e, __bfloat162float(p1.x), acc.z);
        acc.w = fmaf(e, __bfloat162float(p1.y), acc.w);
    }
#pragma unroll
    for (int j = 0; j < KNBR; j++) {
        int idx = __shfl_sync(0xffffffffu, iB, j);
        if (idx >= 0) {
            float e = __shfl_sync(0xffffffffu, eB, j);
            int row = idx & 127;
            unsigned int o = ((unsigned)(idx >> 7) << 16) + hbase + ((unsigned)row << 7)
                           + (cpart ^ (((unsigned)row & 7) << 4));
            uint2 u = __ldg(reinterpret_cast<const uint2*>(g_Vt + o));
            __nv_bfloat162 p0 = *reinterpret_cast<__nv_bfloat162*>(&u.x);
            __nv_bfloat162 p1 = *reinterpret_cast<__nv_bfloat162*>(&u.y);
            acc.x = fmaf(e, __bfloat162float(p0.x), acc.x);
            acc.y = fmaf(e, __bfloat162float(p0.y), acc.y);
            acc.z = fmaf(e, __bfloat162float(p1.x), acc.z);
            acc.w = fmaf(e, __bfloat162float(p1.y), acc.w);
        }
    }
    float inv = 1.0f / (float)(KNBR + validB);
    float gv[4] = {acc.x * inv, acc.y * inv, acc.z * inv, acc.w * inv};
    float hf[4];
#pragma unroll
    for (int q = 0; q < 4; q++)
        hf[q] = __bfloat162float(__float2bfloat16(gv[q]));
    uint2 hi = make_uint2(pack2bf(hf[0], hf[1]), pack2bf(hf[2], hf[3]));
    uint2 lo = make_uint2(pack2bf(gv[0] - hf[0], gv[1] - hf[1]),
                          pack2bf(gv[2] - hf[2], gv[3] - hf[3]));
    unsigned int o = tiled_off(node, lane);
    *reinterpret_cast<uint2*>(g_Gt + o) = hi;
    *reinterpret_cast<uint2*>(g_Gt + 16384 + o) = lo;
}

// =================== smem layout for gemm (dynamic) ===================
// [0]       weights: Wc_h, Wc_l, Wn_h, Wn_l (each 32KB, [n][k] K-major SW128)
// [131072]  A chunk double buffer: 2 x 32KB {hi 16KB | lo 16KB}
// [196608]  mbarriers (2 x 8B)
#define SM_B 0u
#define SM_A 131072u
#define SM_MBAR 196608u
#define SM_TOTAL 196640

// ---------------- Kernel 2: TMA-bulk pipelined HMMA 3-term dual GEMM ----------------
__global__ __launch_bounds__(512, 1)
void gemm_tc(const float* __restrict__ Wvc,
             const float* __restrict__ Wvn,
             const float* __restrict__ bv,
             float* __restrict__ out,
             int n, int ntiles) {
    extern __shared__ char smem[];
    unsigned int sb = smem_u32(smem);
    const int tid = threadIdx.x;
    const int wid = tid >> 5;
    const int lane = tid & 31;

    if (tid == 0) {
        MBARRIER_INIT(sb + SM_MBAR, 1);
        MBARRIER_INIT(sb + SM_MBAR + 8, 1);
    }
    __syncthreads();

    // one 32KB bulk copy per chunk (hi+lo planes of one 64-k half)
    auto issue = [&](int buf, int tile, int s, int h) {
        if (tid == 0) {
            unsigned int mb = sb + SM_MBAR + (unsigned)buf * 8u;
            MBAR_EXPECT_TX(mb, 32768u);
            const unsigned char* src = (s ? g_Gt : g_Vt)
                + ((size_t)tile << 16) + ((size_t)h << 15);
            BULK_G2S(sb + SM_A + (unsigned)buf * 32768u, src, 32768u, mb);
        }
    };

    // kick off first chunk, then convert weights while it flies
    if (blockIdx.x < (unsigned)ntiles) issue(0, blockIdx.x, 0, 0);

    for (int m = 0; m < 2; m++) {
        const float* W = m ? Wvn : Wvc;
        char* bh = smem + SM_B + m * 65536;
        char* bl = bh + 32768;
        for (int idx = tid; idx < 4096; idx += 512) {
            int k  = idx >> 5;
            int n4 = (idx & 31) << 2;
            float4 w = *reinterpret_cast<const float4*>(W + k * FEATS + n4);
            float wv[4] = {w.x, w.y, w.z, w.w};
#pragma unroll
            for (int i = 0; i < 4; i++) {
                __nv_bfloat16 h = __float2bfloat16(wv[i]);
                float hf = __bfloat162float(h);
                __nv_bfloat16 l = __float2bfloat16(wv[i] - hf);
                unsigned int off = sw128(tile_off(n4 + i, k));
                *reinterpret_cast<__nv_bfloat16*>(bh + off) = h;
                *reinterpret_cast<__nv_bfloat16*>(bl + off) = l;
            }
        }
    }

    // ---- per-warp ldmatrix addresses (pure-XOR SW128 form, within-plane) ----
    const int wm = wid & 3;        // 32-row block
    const int wn = wid >> 2;       // 32-col block
    const int mIdx = lane >> 3;
    const int r8 = lane & 7;

    const int rowA = wm * 32 + ((mIdx & 1) << 3) + r8;
    const unsigned int prowA =
        ((unsigned)rowA << 7) ^ (((unsigned)rowA & 7) << 4) ^ (((unsigned)mIdx >> 1) << 4);
    const int rowB = wn * 32 + ((mIdx >> 1) << 3) + r8;
    const unsigned int prowB =
        ((unsigned)rowB << 7) ^ (((unsigned)rowB & 7) << 4) ^ (((unsigned)mIdx & 1) << 4);

    float2 biasj[4];
#pragma unroll
    for (int j = 0; j < 4; j++) {
        int c = wn * 32 + j * 8 + ((lane & 3) << 1);
        biasj[j].x = __ldg(bv + c);
        biasj[j].y = __ldg(bv + c + 1);
    }

    int ph[2] = {0, 0};
    for (int tile = blockIdx.x; tile < ntiles; tile += gridDim.x) {
        float acc[2][4][4];
#pragma unroll
        for (int i = 0; i < 2; i++)
#pragma unroll
            for (int j = 0; j < 4; j++)
#pragma unroll
                for (int q = 0; q < 4; q++) acc[i][j][q] = 0.f;

        int buf = 0;
#pragma unroll
        for (int c = 0; c < 4; c++) {
            const int s = c >> 1, h = c & 1;
            __syncthreads();  // all readers of buf^1 are done
            if (c < 3) {
                issue(buf ^ 1, tile, (c + 1) >> 1, (c + 1) & 1);
            } else {
                int nt = tile + gridDim.x;
                if (nt < ntiles) issue(buf ^ 1, nt, 0, 0);
            }
            MBARRIER_WAIT_PARITY(sb + SM_MBAR + (unsigned)buf * 8u, ph[buf]);
            ph[buf] ^= 1;

            const unsigned int aHp = sb + SM_A + (unsigned)buf * 32768u;
            const unsigned int aLp = aHp + 16384u;
            const unsigned int bHp = sb + SM_B + (unsigned)s * 65536u + (unsigned)h * 16384u;
            const unsigned int bLp = bHp + 32768u;

#pragma unroll
            for (int ks = 0; ks < 4; ks++) {
                const unsigned int Kc = (unsigned)ks << 5;
                unsigned int ah[2][4], al[2][4], bh[2][4], bl[2][4];
                ldsm4(ah[0], aHp + (prowA ^ Kc));
                ldsm4(ah[1], aHp + (prowA ^ 0x800u ^ Kc));
                ldsm4(al[0], aLp + (prowA ^ Kc));
                ldsm4(al[1], aLp + (prowA ^ 0x800u ^ Kc));
                ldsm4(bh[0], bHp + (prowB ^ Kc));
                ldsm4(bh[1], bHp + (prowB ^ 0x800u ^ Kc));
                ldsm4(bl[0], bLp + (prowB ^ Kc));
                ldsm4(bl[1], bLp + (prowB ^ 0x800u ^ Kc));
#pragma unroll
                for (int i = 0; i < 2; i++) {
#pragma unroll
                    for (int j = 0; j < 4; j++) {
                        unsigned int b0h = bh[j >> 1][(j & 1) * 2];
                        unsigned int b1h = bh[j >> 1][(j & 1) * 2 + 1];
                        unsigned int b0l = bl[j >> 1][(j & 1) * 2];
                        unsigned int b1l = bl[j >> 1][(j & 1) * 2 + 1];
                        mma16816(acc[i][j], ah[i], b0h, b1h);  // Ah*Bh
                        mma16816(acc[i][j], ah[i], b0l, b1l);  // Ah*Bl
                        mma16816(acc[i][j], al[i], b0h, b1h);  // Al*Bh
                    }
                }
            }
            buf ^= 1;
        }

        // ---- epilogue (overlaps next tile's chunk0 bulk load) ----
        int row_base = tile * 128 + wm * 32 + (lane >> 2);
#pragma unroll
        for (int i = 0; i < 2; i++) {
            int r0 = row_base + i * 16;
            int r1 = r0 + 8;
#pragma unroll
            for (int j = 0; j < 4; j++) {
                int col = wn * 32 + j * 8 + ((lane & 3) << 1);
                if (r0 < n) {
                    float2 o;
                    o.x = fmaxf(acc[i][j][0] + biasj[j].x, 0.f);
                    o.y = fmaxf(acc[i][j][1] + biasj[j].y, 0.f);
                    *reinterpret_cast<float2*>(out + (long long)r0 * FEATS + col) = o;
                }
                if (r1 < n) {
                    float2 o;
                    o.x = fmaxf(acc[i][j][2] + biasj[j].x, 0.f);
                    o.y = fmaxf(acc[i][j][3] + biasj[j].y, 0.f);
                    *reinterpret_cast<float2*>(out + (long long)r1 * FEATS + col) = o;
                }
            }
        }
    }
}

extern "C" void kernel_launch(void* const* d_in, const int* in_sizes, int n_in,
                              void* d_out, int out_size) {
    const float* vertices = (const float*)d_in[0];
    const int*   nh_idx   = (const int*)d_in[1];
    const int*   int_idx  = (const int*)d_in[2];
    const float* nh_e     = (const float*)d_in[3];
    const float* int_e    = (const float*)d_in[4];
    const float* Wvc      = (const float*)d_in[5];
    const float* Wvn      = (const float*)d_in[6];
    const float* bv       = (const float*)d_in[7];
    float* out = (float*)d_out;

    int n = in_sizes[0] / FEATS;  // 50000

    int n4 = n * 32;
    conv_kernel<<<(n4 + 255) / 256, 256>>>((const float4*)vertices, n4);

    agg_kernel<<<(n + 7) / 8, 256>>>(nh_idx, int_idx, nh_e, int_e, n);

    int ntiles = (n + 127) / 128;
    int grid = ntiles < 148 ? ntiles : 148;
    cudaFuncSetAttribute(gemm_tc, cudaFuncAttributeMaxDynamicSharedMemorySize, SM_TOTAL);
    gemm_tc<<<grid, 512, SM_TOTAL>>>(Wvc, Wvn, bv, out, n, ntiles);
}

// round 12
// speedup vs baseline: 1.5075x; 1.5075x over previous
#include <cuda_runtime.h>
#include <cuda_fp16.h>

#define NODES_MAX 50000
#define FEATS 128
#define KNBR 20

// fp16 planes, row-major [N][128]
__device__ __half g_Vh[NODES_MAX * FEATS];
__device__ __half g_Gh[NODES_MAX * FEATS];

// =================== helpers ===================
__device__ __forceinline__ unsigned int smem_u32(const void* p) {
    unsigned int a;
    asm("{ .reg .u64 t; cvta.to.shared.u64 t, %1; cvt.u32.u64 %0, t; }"
        : "=r"(a) : "l"(p));
    return a;
}
__device__ __forceinline__ void ldsm4(unsigned int r[4], unsigned int addr) {
    asm volatile("ldmatrix.sync.aligned.m8n8.x4.shared.b16 {%0,%1,%2,%3}, [%4];"
                 : "=r"(r[0]), "=r"(r[1]), "=r"(r[2]), "=r"(r[3])
                 : "r"(addr));
}
__device__ __forceinline__ void mma16816h(float c[4], const unsigned int a[4],
                                          unsigned int b0, unsigned int b1) {
    asm volatile(
        "mma.sync.aligned.m16n8k16.row.col.f32.f16.f16.f32 "
        "{%0,%1,%2,%3}, {%4,%5,%6,%7}, {%8,%9}, {%0,%1,%2,%3};"
        : "+f"(c[0]), "+f"(c[1]), "+f"(c[2]), "+f"(c[3])
        : "r"(a[0]), "r"(a[1]), "r"(a[2]), "r"(a[3]), "r"(b0), "r"(b1));
}
__device__ __forceinline__ void cp16(unsigned int dst, const void* src) {
    asm volatile("cp.async.cg.shared.global [%0], [%1], 16;"
                 :: "r"(dst), "l"(__cvta_generic_to_global(src)) : "memory");
}
#define CP_COMMIT() asm volatile("cp.async.commit_group;" ::: "memory")
#define CP_WAIT1()  asm volatile("cp.async.wait_group 1;" ::: "memory")

__device__ __forceinline__ unsigned int sw128(unsigned int b) {
    return b ^ ((b >> 3) & 0x70);
}
// [128 x 128] fp16 K-major tile = two 64-k planes of 16KB, 128B rows
__device__ __forceinline__ unsigned int tile_off(int row, int k) {
    return ((unsigned)(k >> 6) << 14) + ((unsigned)row << 7) + ((unsigned)(k & 63) << 1);
}
__device__ __forceinline__ unsigned int pack2h(float a, float b) {
    __half2 p = __floats2half2_rn(a, b);
    return *reinterpret_cast<unsigned int*>(&p);
}

// ---------------- Kernel 0: V -> fp16 plane ----------------
__global__ void conv_kernel(const float4* __restrict__ X4, int n4) {
    int i = blockIdx.x * blockDim.x + threadIdx.x;
    if (i < n4) {
        float4 v = X4[i];
        uint2 u = make_uint2(pack2h(v.x, v.y), pack2h(v.z, v.w));
        reinterpret_cast<uint2*>(g_Vh)[i] = u;
    }
}

// ---------------- Kernel 1: gather-aggregate from fp16 V ----------------
__global__ void agg_kernel(const int* __restrict__ nh_idx,
                           const int* __restrict__ int_idx,
                           const float* __restrict__ nh_e,
                           const float* __restrict__ int_e,
                           int n) {
    int node = blockIdx.x * (blockDim.x >> 5) + (threadIdx.x >> 5);
    if (node >= n) return;
    int lane = threadIdx.x & 31;
    const uint2* Vb2 = reinterpret_cast<const uint2*>(g_Vh);

    int   iA = -1, iB = -1;
    float eA = 0.f, eB = 0.f;
    if (lane < KNBR) {
        int base = node * KNBR + lane;
        iA = nh_idx[base];
        eA = nh_e[base];
        iB = int_idx[base];
        eB = int_e[base];
    }
    int validB = __popc(__ballot_sync(0xffffffffu, (lane < KNBR) && (iB >= 0)));

    float4 acc = make_float4(0.f, 0.f, 0.f, 0.f);
#pragma unroll
    for (int j = 0; j < KNBR; j++) {
        int   idx = __shfl_sync(0xffffffffu, iA, j);
        float e   = __shfl_sync(0xffffffffu, eA, j);
        uint2 u   = __ldg(&Vb2[idx * 32 + lane]);
        float2 p0 = __half22float2(*reinterpret_cast<__half2*>(&u.x));
        float2 p1 = __half22float2(*reinterpret_cast<__half2*>(&u.y));
        acc.x = fmaf(e, p0.x, acc.x);
        acc.y = fmaf(e, p0.y, acc.y);
        acc.z = fmaf(e, p1.x, acc.z);
        acc.w = fmaf(e, p1.y, acc.w);
    }
#pragma unroll
    for (int j = 0; j < KNBR; j++) {
        int idx = __shfl_sync(0xffffffffu, iB, j);
        if (idx >= 0) {
            float e  = __shfl_sync(0xffffffffu, eB, j);
            uint2 u  = __ldg(&Vb2[idx * 32 + lane]);
            float2 p0 = __half22float2(*reinterpret_cast<__half2*>(&u.x));
            float2 p1 = __half22float2(*reinterpret_cast<__half2*>(&u.y));
            acc.x = fmaf(e, p0.x, acc.x);
            acc.y = fmaf(e, p0.y, acc.y);
            acc.z = fmaf(e, p1.x, acc.z);
            acc.w = fmaf(e, p1.y, acc.w);
        }
    }
    float inv = 1.0f / (float)(KNBR + validB);
    uint2 o = make_uint2(pack2h(acc.x * inv, acc.y * inv),
                         pack2h(acc.z * inv, acc.w * inv));
    reinterpret_cast<uint2*>(g_Gh)[node * 32 + lane] = o;
}

// =================== smem layout for gemm (dynamic) ===================
// [0]       weights: Wc (32KB), Wn (32KB) -- fp16 [n][k] K-major SW128
// [65536]   A chunk double buffer: 2 x 16KB
#define SM_B 0u
#define SM_A 65536u
#define SM_TOTAL 98304

// ---------------- Kernel 2: pipelined fp16 HMMA dual GEMM ----------------
__global__ __launch_bounds__(512, 1)
void gemm_tc(const float* __restrict__ Wvc,
             const float* __restrict__ Wvn,
             const float* __restrict__ bv,
             float* __restrict__ out,
             int n, int ntiles) {
    extern __shared__ char smem[];
    unsigned int sb = smem_u32(smem);
    const int tid = threadIdx.x;
    const int wid = tid >> 5;
    const int lane = tid & 31;

    // chunk loader: 16KB (one 64-k half) via cp.async
    auto load_chunk = [&](int buf, int tile, int s, int h) {
        const __half* src = s ? g_Gh : g_Vh;
        unsigned int dstBase = sb + SM_A + (unsigned)buf * 16384u;
        int idx = tid;                 // 0..511; 2 units per thread
#pragma unroll
        for (int i = 0; i < 2; i++) {
            int row = idx >> 3;
            int u   = idx & 7;         // 16B unit within 128B row-half
            int gr = tile * 128 + row;
            if (gr >= n) gr = n - 1;
            unsigned int off = sw128((unsigned)(row * 128 + u * 16));
            cp16(dstBase + off, (const char*)src + (long long)gr * 256 + h * 128 + u * 16);
            idx += 512;
        }
    };

    // kick off first chunk, then convert weights while it flies
    if (blockIdx.x < (unsigned)ntiles) load_chunk(0, blockIdx.x, 0, 0);
    CP_COMMIT();

    for (int m = 0; m < 2; m++) {
        const float* W = m ? Wvn : Wvc;
        char* bp = smem + SM_B + m * 32768;
        for (int idx = tid; idx < 4096; idx += 512) {
            int k  = idx >> 5;
            int n4 = (idx & 31) << 2;
            float4 w = *reinterpret_cast<const float4*>(W + k * FEATS + n4);
            float wv[4] = {w.x, w.y, w.z, w.w};
#pragma unroll
            for (int i = 0; i < 4; i++) {
                unsigned int off = sw128(tile_off(n4 + i, k));
                *reinterpret_cast<__half*>(bp + off) = __float2half_rn(wv[i]);
            }
        }
    }

    // ---- per-warp ldmatrix addresses (pure-XOR SW128 form, within-plane) ----
    const int wm = wid & 3;        // 32-row block
    const int wn = wid >> 2;       // 32-col block
    const int mIdx = lane >> 3;
    const int r8 = lane & 7;

    const int rowA = wm * 32 + ((mIdx & 1) << 3) + r8;
    const unsigned int prowA =
        ((unsigned)rowA << 7) ^ (((unsigned)rowA & 7) << 4) ^ (((unsigned)mIdx >> 1) << 4);
    const int rowB = wn * 32 + ((mIdx >> 1) << 3) + r8;
    const unsigned int prowB =
        ((unsigned)rowB << 7) ^ (((unsigned)rowB & 7) << 4) ^ (((unsigned)mIdx & 1) << 4);

    float2 biasj[4];
#pragma unroll
    for (int j = 0; j < 4; j++) {
        int c = wn * 32 + j * 8 + ((lane & 3) << 1);
        biasj[j].x = __ldg(bv + c);
        biasj[j].y = __ldg(bv + c + 1);
    }

    for (int tile = blockIdx.x; tile < ntiles; tile += gridDim.x) {
        float acc[2][4][4];
#pragma unroll
        for (int i = 0; i < 2; i++)
#pragma unroll
            for (int j = 0; j < 4; j++)
#pragma unroll
                for (int q = 0; q < 4; q++) acc[i][j][q] = 0.f;

        int buf = 0;
#pragma unroll
        for (int c = 0; c < 4; c++) {
            const int s = c >> 1, h = c & 1;
            __syncthreads();  // prior MMA readers of buf^1 are done
            if (c < 3) {
                load_chunk(buf ^ 1, tile, (c + 1) >> 1, (c + 1) & 1);
            } else {
                int nt = tile + gridDim.x;
                if (nt < ntiles) load_chunk(buf ^ 1, nt, 0, 0);
            }
            CP_COMMIT();
            CP_WAIT1();       // current chunk's data has landed (per-thread)
            __syncthreads();  // ... and is visible CTA-wide

            const unsigned int aP = sb + SM_A + (unsigned)buf * 16384u;
            const unsigned int bP = sb + SM_B + (unsigned)s * 32768u + (unsigned)h * 16384u;

#pragma unroll
            for (int ks = 0; ks < 4; ks++) {
                const unsigned int Kc = (unsigned)ks << 5;
                unsigned int ah[2][4], bh[2][4];
                ldsm4(ah[0], aP + (prowA ^ Kc));
                ldsm4(ah[1], aP + (prowA ^ 0x800u ^ Kc));
                ldsm4(bh[0], bP + (prowB ^ Kc));
                ldsm4(bh[1], bP + (prowB ^ 0x800u ^ Kc));
#pragma unroll
                for (int i = 0; i < 2; i++) {
#pragma unroll
                    for (int j = 0; j < 4; j++) {
                        unsigned int b0 = bh[j >> 1][(j & 1) * 2];
                        unsigned int b1 = bh[j >> 1][(j & 1) * 2 + 1];
                        mma16816h(acc[i][j], ah[i], b0, b1);
                    }
                }
            }
            buf ^= 1;
        }

        // ---- epilogue (overlaps next tile's chunk0 prefetch) ----
        int row_base = tile * 128 + wm * 32 + (lane >> 2);
#pragma unroll
        for (int i = 0; i < 2; i++) {
            int r0 = row_base + i * 16;
            int r1 = r0 + 8;
#pragma unroll
            for (int j = 0; j < 4; j++) {
                int col = wn * 32 + j * 8 + ((lane & 3) << 1);
                if (r0 < n) {
                    float2 o;
                    o.x = fmaxf(acc[i][j][0] + biasj[j].x, 0.f);
                    o.y = fmaxf(acc[i][j][1] + biasj[j].y, 0.f);
                    *reinterpret_cast<float2*>(out + (long long)r0 * FEATS + col) = o;
                }
                if (r1 < n) {
                    float2 o;
                    o.x = fmaxf(acc[i][j][2] + biasj[j].x, 0.f);
                    o.y = fmaxf(acc[i][j][3] + biasj[j].y, 0.f);
                    *reinterpret_cast<float2*>(out + (long long)r1 * FEATS + col) = o;
                }
            }
        }
    }
}

extern "C" void kernel_launch(void* const* d_in, const int* in_sizes, int n_in,
                              void* d_out, int out_size) {
    const float* vertices = (const float*)d_in[0];
    const int*   nh_idx   = (const int*)d_in[1];
    const int*   int_idx  = (const int*)d_in[2];
    const float* nh_e     = (const float*)d_in[3];
    const float* int_e    = (const float*)d_in[4];
    const float* Wvc      = (const float*)d_in[5];
    const float* Wvn      = (const float*)d_in[6];
    const float* bv       = (const float*)d_in[7];
    float* out = (float*)d_out;

    int n = in_sizes[0] / FEATS;  // 50000

    int n4 = n * 32;
    conv_kernel<<<(n4 + 255) / 256, 256>>>((const float4*)vertices, n4);

    agg_kernel<<<(n + 7) / 8, 256>>>(nh_idx, int_idx, nh_e, int_e, n);

    int ntiles = (n + 127) / 128;
    int grid = ntiles < 148 ? ntiles : 148;
    cudaFuncSetAttribute(gemm_tc, cudaFuncAttributeMaxDynamicSharedMemorySize, SM_TOTAL);
    gemm_tc<<<grid, 512, SM_TOTAL>>>(Wvc, Wvn, bv, out, n, ntiles);
}